// round 14
// baseline (speedup 1.0000x reference)
#include <cuda_runtime.h>
#include <cuda_bf16.h>
#include <cstdint>

// ---------------------------------------------------------------------------
// ChannelWise position-attention via generic mma.sync (compute_103-safe).
//   Q = feat_b^T [N,32] bf16 (pre-scaled by log2e), K = feat_c^T [N,32] bf16,
//   V = feat_d channel-major [256,N] bf16,  N = 4096, B = 4.
//   out = alpha * (softmax(QK^T) V)^T + (1-alpha) * x
// Pool FUSED into projection GEMM (bf16 mma).
// Attention: 64-row CTA, 256 thr, 32-token KV tiles, 2 CTAs/SM (occupancy
// experiment: latency-bound at 4 warps/SMSP per R13 ncu evidence).
// ---------------------------------------------------------------------------

#define NTOK 4096
#define BATCH 4
#define NEG_BIG (-3.402823466e38f)
#define LOG2E 1.4426950408889634f

__device__ __nv_bfloat16 g_wb16[320 * 512];            // [o][k] bf16
__device__ float g_bias[320];
__device__ __nv_bfloat16 g_qb[BATCH * NTOK * 32];      // [b][n][32] (x log2e)
__device__ __nv_bfloat16 g_kb[BATCH * NTOK * 32];      // [b][n][32]
__device__ __nv_bfloat16 g_vb[BATCH * 256 * NTOK];     // [b][c][n]

extern __shared__ char smem_dyn[];

// ======================= PTX helpers ======================================
__device__ __forceinline__ uint32_t smem_u32(const void* p) {
    uint32_t a;
    asm("{ .reg .u64 t; cvta.to.shared.u64 t, %1; cvt.u32.u64 %0, t; }"
        : "=r"(a) : "l"(p));
    return a;
}
__device__ __forceinline__ uint32_t pack_bf16x2(float lo, float hi) {
    uint32_t r;
    asm("cvt.rn.bf16x2.f32 %0, %1, %2;" : "=r"(r) : "f"(hi), "f"(lo));
    return r;
}
__device__ __forceinline__ float ex2(float x) {
    float y;
    asm("ex2.approx.f32 %0, %1;" : "=f"(y) : "f"(x));
    return y;
}
__device__ __forceinline__ void ldsm4(uint32_t r[4], uint32_t addr) {
    asm volatile("ldmatrix.sync.aligned.m8n8.x4.shared.b16 {%0,%1,%2,%3}, [%4];"
                 : "=r"(r[0]), "=r"(r[1]), "=r"(r[2]), "=r"(r[3]) : "r"(addr));
}
__device__ __forceinline__ void ldsm4t(uint32_t r[4], uint32_t addr) {
    asm volatile(
        "ldmatrix.sync.aligned.m8n8.x4.trans.shared.b16 {%0,%1,%2,%3}, [%4];"
        : "=r"(r[0]), "=r"(r[1]), "=r"(r[2]), "=r"(r[3]) : "r"(addr));
}
__device__ __forceinline__ void mma_bf16(float d[4], const uint32_t a[4],
                                         uint32_t b0, uint32_t b1) {
    asm volatile(
        "mma.sync.aligned.m16n8k16.row.col.f32.bf16.bf16.f32 "
        "{%0,%1,%2,%3},{%4,%5,%6,%7},{%8,%9},{%0,%1,%2,%3};"
        : "+f"(d[0]), "+f"(d[1]), "+f"(d[2]), "+f"(d[3])
        : "r"(a[0]), "r"(a[1]), "r"(a[2]), "r"(a[3]), "r"(b0), "r"(b1));
}
__device__ __forceinline__ void cp16(uint32_t dst, const void* src) {
    asm volatile("cp.async.cg.shared.global [%0], [%1], 16;"
                 :: "r"(dst), "l"(src));
}
#define CP_COMMIT() asm volatile("cp.async.commit_group;" ::: "memory")
#define CP_WAIT0()  asm volatile("cp.async.wait_group 0;" ::: "memory")

// ---------------------------------------------------------------------------
// Kernel 1: W -> bf16 [o][k] + bias. 80 blocks x 512 thr, float4 per thread.
// ---------------------------------------------------------------------------
__global__ void prep_w(const float* __restrict__ wb, const float* __restrict__ bb,
                       const float* __restrict__ wc, const float* __restrict__ bc,
                       const float* __restrict__ wd, const float* __restrict__ bd) {
    int g = blockIdx.x * 512 + threadIdx.x;
    int o = g >> 7, k4 = (g & 127) << 2;
    const float* src;
    if (o < 32)       src = wb + o * 512;
    else if (o < 64)  src = wc + (o - 32) * 512;
    else              src = wd + (o - 64) * 512;
    float4 v = *(const float4*)(src + k4);
    *(uint2*)(g_wb16 + o * 512 + k4) =
        make_uint2(pack_bf16x2(v.x, v.y), pack_bf16x2(v.z, v.w));
    if ((g & 127) == 0)
        g_bias[o] = (o < 32) ? bb[o] : (o < 64 ? bc[o - 32] : bd[o - 64]);
}

// ---------------------------------------------------------------------------
// Kernel 2: FUSED pool + projection GEMM (unchanged from R13).
// ---------------------------------------------------------------------------
#define XT(i)    ((i) * 34816)
#define CATA     69632
#define CATB     78336
#define PWA(i)   (87040 + (i) * 25600)
#define PWB(i)   (138240 + (i) * 25600)
#define PRJ_SMEM 189440

__global__ __launch_bounds__(512) void proj_mma(const float* __restrict__ xin) {
    const uint32_t sb = smem_u32(smem_dyn);
    const int tid = threadIdx.x, w = tid >> 5, l = tid & 31;
    const int mw = w >> 2, nw = w & 3;
    const int mt_base = mw * 32, o0w = nw * 80;
    const int ntile = blockIdx.x, b = blockIdx.y;
    const int n0 = ntile * 128;
    const int H0 = ntile * 2;
    const bool row0v = (ntile > 0);
    const bool row3v = (ntile < 31);
    const float* xg = xin + ((size_t)b << 20);

    float acc[2][10][4];
#pragma unroll
    for (int i = 0; i < 2; i++)
#pragma unroll
        for (int j = 0; j < 10; j++)
#pragma unroll
            for (int k = 0; k < 4; k++) acc[i][j][k] = 0.f;

#define PRJ_LOADX(buf, p_)                                                     \
    do {                                                                       \
        int pch_ = (p_) * 32;                                                  \
        _Pragma("unroll")                                                      \
        for (int i_ = 0; i_ < 4; ++i_) {                                       \
            int c_ = tid + i_ * 512;                                           \
            int ch_ = c_ >> 6, row_ = (c_ >> 4) & 3, pp_ = c_ & 15;            \
            uint32_t off_ =                                                    \
                (uint32_t)(XT(buf) + ch_ * 1088 + row_ * 272 + pp_ * 16);      \
            int hh_ = H0 - 1 + row_;                                           \
            if ((unsigned)hh_ < 64u)                                           \
                cp16(sb + off_,                                                \
                     xg + ((size_t)(pch_ + ch_) << 12) + (hh_ << 6) + pp_ * 4);\
            else                                                               \
                *(float4*)(smem_dyn + off_) = make_float4(0.f, 0.f, 0.f, 0.f); \
        }                                                                      \
        for (int e_ = tid; e_ < 1280; e_ += 512) {                             \
            int ro_ = e_ >> 2, pq_ = e_ & 3;                                   \
            cp16(sb + PWA(buf) + ro_ * 80 + pq_ * 16,                          \
                 g_wb16 + ro_ * 512 + pch_ + pq_ * 8);                         \
            cp16(sb + PWB(buf) + ro_ * 80 + pq_ * 16,                          \
                 g_wb16 + ro_ * 512 + 256 + pch_ + pq_ * 8);                   \
        }                                                                      \
    } while (0)

#define PRJ_MMA_CHUNK(cbase, wbase)                                            \
    do {                                                                       \
        _Pragma("unroll")                                                      \
        for (int ks = 0; ks < 2; ++ks) {                                       \
            uint32_t a_[2][4];                                                 \
            _Pragma("unroll")                                                  \
            for (int mt = 0; mt < 2; ++mt) {                                   \
                uint32_t addr_ = (cbase) +                                     \
                    (uint32_t)((ks * 16 + (l & 7) + ((l >> 4) << 3)) * 272 +   \
                               (mt_base + mt * 16 + (((l >> 3) & 1) << 3)) * 2);\
                ldsm4t(a_[mt], addr_);                                         \
            }                                                                  \
            _Pragma("unroll")                                                  \
            for (int bt = 0; bt < 5; ++bt) {                                   \
                uint32_t b4_[4];                                               \
                uint32_t addr_ = (wbase) +                                     \
                    (uint32_t)((o0w + bt * 16 + (l & 15)) * 80 + ks * 32 +     \
                               ((l >> 4) << 4));                               \
                ldsm4(b4_, addr_);                                             \
                mma_bf16(acc[0][bt * 2],     a_[0], b4_[0], b4_[2]);           \
                mma_bf16(acc[0][bt * 2 + 1], a_[0], b4_[1], b4_[3]);           \
                mma_bf16(acc[1][bt * 2],     a_[1], b4_[0], b4_[2]);           \
                mma_bf16(acc[1][bt * 2 + 1], a_[1], b4_[1], b4_[3]);           \
            }                                                                  \
        }                                                                      \
    } while (0)

    PRJ_LOADX(0, 0);
    CP_COMMIT();

    const int lane16 = l & 15;
    const int tr = (l >> 4) & 1;

#pragma unroll 1
    for (int p = 0; p < 8; ++p) {
        const int pb = p & 1;
        CP_WAIT0();
        __syncthreads();
        if (p + 1 < 8) {
            PRJ_LOADX((p + 1) & 1, p + 1);
            CP_COMMIT();
        }
        {
            const bool fA = (tr == 1) || row0v;
            const bool fC = (tr == 0) || row3v;
            const float inv9 = 1.f / 9.f;
#pragma unroll
            for (int i = 0; i < 2; ++i) {
                int ch = (tid + i * 512) >> 5;
                uint32_t xb =
                    (uint32_t)(XT(pb) + ch * 1088 + tr * 272 + lane16 * 16);
                float4 vA = *(const float4*)(smem_dyn + xb);
                float4 vB = *(const float4*)(smem_dyn + xb + 272);
                float4 vC = *(const float4*)(smem_dyn + xb + 544);
                float4 cs;
                cs.x = vA.x + vB.x + vC.x;
                cs.y = vA.y + vB.y + vC.y;
                cs.z = vA.z + vB.z + vC.z;
                cs.w = vA.w + vB.w + vC.w;
                float4 m4 = vB;
                if (fA) {
                    m4.x = fmaxf(m4.x, vA.x); m4.y = fmaxf(m4.y, vA.y);
                    m4.z = fmaxf(m4.z, vA.z); m4.w = fmaxf(m4.w, vA.w);
                }
                if (fC) {
                    m4.x = fmaxf(m4.x, vC.x); m4.y = fmaxf(m4.y, vC.y);
                    m4.z = fmaxf(m4.z, vC.z); m4.w = fmaxf(m4.w, vC.w);
                }
                float csL = __shfl_up_sync(0xffffffffu, cs.w, 1, 16);
                float mL  = __shfl_up_sync(0xffffffffu, m4.w, 1, 16);
                float csR = __shfl_down_sync(0xffffffffu, cs.x, 1, 16);
                float mR  = __shfl_down_sync(0xffffffffu, m4.x, 1, 16);
                if (lane16 == 0)  { csL = 0.f; mL = NEG_BIG; }
                if (lane16 == 15) { csR = 0.f; mR = NEG_BIG; }
                float a0 = (csL + cs.x + cs.y) * inv9;
                float a1 = (cs.x + cs.y + cs.z) * inv9;
                float a2 = (cs.y + cs.z + cs.w) * inv9;
                float a3 = (cs.z + cs.w + csR) * inv9;
                float M0 = fmaxf(fmaxf(mL, m4.x), m4.y);
                float M1 = fmaxf(fmaxf(m4.x, m4.y), m4.z);
                float M2 = fmaxf(fmaxf(m4.y, m4.z), m4.w);
                float M3 = fmaxf(fmaxf(m4.z, m4.w), mR);
                uint32_t co = (uint32_t)(ch * 272 + (tr * 64 + lane16 * 4) * 2);
                *(uint2*)(smem_dyn + CATA + co) =
                    make_uint2(pack_bf16x2(a0, a1), pack_bf16x2(a2, a3));
                *(uint2*)(smem_dyn + CATB + co) =
                    make_uint2(pack_bf16x2(M0, M1), pack_bf16x2(M2, M3));
            }
        }
        __syncthreads();
        PRJ_MMA_CHUNK(sb + CATA, sb + PWA(pb));
        PRJ_MMA_CHUNK(sb + CATB, sb + PWB(pb));
    }
    __syncthreads();

    float* stg = (float*)smem_dyn;
#pragma unroll
    for (int mt = 0; mt < 2; ++mt) {
        int m = mt_base + mt * 16 + (l >> 2);
#pragma unroll
        for (int t = 0; t < 10; ++t) {
            int o = o0w + t * 8 + (l & 3) * 2;
            float b0v = g_bias[o], b1v = g_bias[o + 1];
            stg[o * 133 + m]           = acc[mt][t][0] + b0v;
            stg[(o + 1) * 133 + m]     = acc[mt][t][1] + b1v;
            stg[o * 133 + m + 8]       = acc[mt][t][2] + b0v;
            stg[(o + 1) * 133 + m + 8] = acc[mt][t][3] + b1v;
        }
    }
    __syncthreads();
    for (int e = tid; e < 128 * 16; e += 512) {
        int o2 = e & 15, nl = e >> 4;
        *(uint32_t*)(g_qb + ((size_t)b * NTOK + n0 + nl) * 32 + 2 * o2) =
            pack_bf16x2(LOG2E * stg[(2 * o2) * 133 + nl],
                        LOG2E * stg[(2 * o2 + 1) * 133 + nl]);
    }
    for (int e = tid; e < 128 * 16; e += 512) {
        int o2 = e & 15, nl = e >> 4;
        *(uint32_t*)(g_kb + ((size_t)b * NTOK + n0 + nl) * 32 + 2 * o2) =
            pack_bf16x2(stg[(32 + 2 * o2) * 133 + nl],
                        stg[(33 + 2 * o2) * 133 + nl]);
    }
    for (int e = tid; e < 256 * 64; e += 512) {
        int ch = e >> 6, tp = e & 63;
        float f0 = stg[(64 + ch) * 133 + 2 * tp];
        float f1 = stg[(64 + ch) * 133 + 2 * tp + 1];
        *(uint32_t*)(g_vb + ((size_t)(b * 256 + ch)) * NTOK + n0 + 2 * tp) =
            pack_bf16x2(f0, f1);
    }
}

// ---------------------------------------------------------------------------
// Kernel 3: mma.sync attention, 2 CTAs/SM. CTA = 64 rows, 256 thr (8 warps),
// 32-token KV tiles (128 iters). S: rg=w&3 rows, th=w>>2 token half (4 mma);
// PV: channels w*32..+31, all 64 rows (32 mma).
// smem: K[2][32 tok][80B] | V[2][256 ch][80B] | P[64][80B] | L[64]f32
// ---------------------------------------------------------------------------
#define AK(i) ((i) * 2560)
#define AV(i) (5120 + (i) * 20480)
#define AP 46080
#define AL 51200
#define ATT_SMEM 51456

__device__ __forceinline__ void load_tiles(uint32_t sb, int buf,
                                           const __nv_bfloat16* Kg,
                                           const __nv_bfloat16* Vg, int jt,
                                           int tid) {
    if (tid < 128) {                           // K: 32 tok x 64B
        const __nv_bfloat16* ks = Kg + (size_t)jt * 32 * 32;
        int tok = tid >> 2, p = tid & 3;
        cp16(sb + AK(buf) + tok * 80 + p * 16, ks + tok * 32 + p * 8);
    }
    const __nv_bfloat16* vs = Vg + jt * 32;    // V: 256 ch x 64B
    uint32_t vd = sb + AV(buf);
#pragma unroll
    for (int i = 0; i < 4; ++i) {
        int c = tid + i * 256;
        int ch = c >> 2, p = c & 3;
        cp16(vd + ch * 80 + p * 16, vs + (size_t)ch * NTOK + p * 8);
    }
}

__global__ __launch_bounds__(256, 2) void attn_mma(
    const float* __restrict__ Xg, const float* __restrict__ alpha_p,
    float* __restrict__ Og) {
    const uint32_t sb = smem_u32(smem_dyn);
    float* Lsm = (float*)(smem_dyn + AL);
    const int tid = threadIdx.x, w = tid >> 5, l = tid & 31;
    const int rg = w & 3, th = w >> 2;         // S mapping
    const int mt = blockIdx.x, b = blockIdx.y;
    const int m0 = mt * 64;
    const int r0 = l >> 2, kb = l & 3;

    if (tid < 64) Lsm[tid] = 0.f;

    // ---- Q bf16 A-fragments (2 k-steps), rows rg*16 + r0 (+8) ----
    uint32_t qa[2][4];
    {
        const uint32_t* Qg =
            (const uint32_t*)(g_qb + ((size_t)b * NTOK + m0 + rg * 16) * 32);
#pragma unroll
        for (int s_ = 0; s_ < 2; ++s_) {
            qa[s_][0] = Qg[r0 * 16 + s_ * 8 + kb];
            qa[s_][1] = Qg[(r0 + 8) * 16 + s_ * 8 + kb];
            qa[s_][2] = Qg[r0 * 16 + s_ * 8 + kb + 4];
            qa[s_][3] = Qg[(r0 + 8) * 16 + s_ * 8 + kb + 4];
        }
    }

    float o[2][8][4];
#pragma unroll
    for (int i = 0; i < 2; i++)
#pragma unroll
        for (int j = 0; j < 8; j++)
#pragma unroll
            for (int k = 0; k < 4; k++) o[i][j][k] = 0.f;

    const __nv_bfloat16* Kg = g_kb + (size_t)b * NTOK * 32;
    const __nv_bfloat16* Vg = g_vb + (size_t)b * 256 * NTOK;

    load_tiles(sb, 0, Kg, Vg, 0, tid);
    CP_COMMIT();

#pragma unroll 1
    for (int jt = 0; jt < 128; ++jt) {
        const int cur = jt & 1;
        CP_WAIT0();
        __syncthreads();
        if (jt + 1 < 128) {
            load_tiles(sb, 1 - cur, Kg, Vg, jt + 1, tid);
            CP_COMMIT();
        }
        const uint32_t* K32 = (const uint32_t*)(smem_dyn + AK(cur));
        const uint32_t* V32 = (const uint32_t*)(smem_dyn + AV(cur));
        uint32_t* P32 = (uint32_t*)(smem_dyn + AP);

        // ---- S = Q K^T (bf16 m16n8k16, 4 mma; log2 domain) ----
        float s[2][4];
#pragma unroll
        for (int i = 0; i < 2; i++)
#pragma unroll
            for (int j = 0; j < 4; j++) s[i][j] = 0.f;
#pragma unroll
        for (int nt = 0; nt < 2; ++nt) {
            int trow = (th * 16 + nt * 8 + r0) * 20;   // 80B pitch
#pragma unroll
            for (int s_ = 0; s_ < 2; ++s_) {
                uint32_t b0 = K32[trow + s_ * 8 + kb];
                uint32_t b1 = K32[trow + s_ * 8 + kb + 4];
                mma_bf16(s[nt], qa[s_], b0, b1);
            }
        }

        // ---- exp2, pack bf16 P, row-sum partials ----
        float t0 = 0.f, t1 = 0.f;
#pragma unroll
        for (int nt = 0; nt < 2; ++nt) {
            float p0 = ex2(s[nt][0]);
            float p1 = ex2(s[nt][1]);
            float p2 = ex2(s[nt][2]);
            float p3 = ex2(s[nt][3]);
            t0 += p0 + p1;
            t1 += p2 + p3;
            int tp = th * 8 + nt * 4 + kb;
            P32[(rg * 16 + r0) * 20 + tp] = pack_bf16x2(p0, p1);
            P32[(rg * 16 + r0 + 8) * 20 + tp] = pack_bf16x2(p2, p3);
        }
        t0 += __shfl_xor_sync(0xffffffffu, t0, 1);
        t0 += __shfl_xor_sync(0xffffffffu, t0, 2);
        t1 += __shfl_xor_sync(0xffffffffu, t1, 1);
        t1 += __shfl_xor_sync(0xffffffffu, t1, 2);
        if (kb == 0) {
            atomicAdd(&Lsm[rg * 16 + r0], t0);
            atomicAdd(&Lsm[rg * 16 + r0 + 8], t1);
        }
        __syncthreads();

        // ---- O^T += V' P^T (bf16 mma): channels w*32..+31, 64 rows ----
        uint32_t va[2][2][4];
#pragma unroll
        for (int m = 0; m < 2; ++m) {
            int cb = w * 32 + m * 16;
#pragma unroll
            for (int ks = 0; ks < 2; ++ks) {
                va[m][ks][0] = V32[(cb + r0) * 20 + ks * 8 + kb];
                va[m][ks][1] = V32[(cb + 8 + r0) * 20 + ks * 8 + kb];
                va[m][ks][2] = V32[(cb + r0) * 20 + ks * 8 + 4 + kb];
                va[m][ks][3] = V32[(cb + 8 + r0) * 20 + ks * 8 + 4 + kb];
            }
        }
#pragma unroll
        for (int nt = 0; nt < 8; ++nt) {
            int prow = nt * 8 + r0;
#pragma unroll
            for (int ks = 0; ks < 2; ++ks) {
                uint32_t b0 = P32[prow * 20 + ks * 8 + kb];
                uint32_t b1 = P32[prow * 20 + ks * 8 + 4 + kb];
                mma_bf16(o[0][nt], va[0][ks], b0, b1);
                mma_bf16(o[1][nt], va[1][ks], b0, b1);
            }
        }
    }
    __syncthreads();

    // ---- epilogue ----
    float alpha = *alpha_p;
    if (tid < 64) Lsm[tid] = alpha / Lsm[tid];
    __syncthreads();
    float beta = 1.0f - alpha;
#pragma unroll
    for (int m = 0; m < 2; ++m) {
        int ch = w * 32 + m * 16 + r0;
#pragma unroll
        for (int nt = 0; nt < 8; ++nt) {
            int r = nt * 8 + 2 * kb;
            float i0 = Lsm[r], i1 = Lsm[r + 1];
            size_t g0 = ((size_t)(b * 256 + ch)) * NTOK + m0 + r;
            float2 xv = *(const float2*)(Xg + g0);
            float2 ov = make_float2(o[m][nt][0] * i0 + beta * xv.x,
                                    o[m][nt][1] * i1 + beta * xv.y);
            *(float2*)(Og + g0) = ov;
            size_t g1 = g0 + (size_t)8 * NTOK;
            float2 xv2 = *(const float2*)(Xg + g1);
            float2 ov2 = make_float2(o[m][nt][2] * i0 + beta * xv2.x,
                                     o[m][nt][3] * i1 + beta * xv2.y);
            *(float2*)(Og + g1) = ov2;
        }
    }
}

// ---------------------------------------------------------------------------
extern "C" void kernel_launch(void* const* d_in, const int* in_sizes, int n_in,
                              void* d_out, int out_size) {
    const float* x     = (const float*)d_in[0];
    const float* wb    = (const float*)d_in[1];
    const float* bb    = (const float*)d_in[2];
    const float* wc    = (const float*)d_in[3];
    const float* bc    = (const float*)d_in[4];
    const float* wd    = (const float*)d_in[5];
    const float* bd    = (const float*)d_in[6];
    const float* alpha = (const float*)d_in[7];
    float* out = (float*)d_out;

    cudaFuncSetAttribute(proj_mma, cudaFuncAttributeMaxDynamicSharedMemorySize,
                         PRJ_SMEM);
    cudaFuncSetAttribute(attn_mma, cudaFuncAttributeMaxDynamicSharedMemorySize,
                         ATT_SMEM);

    prep_w<<<80, 512>>>(wb, bb, wc, bc, wd, bd);

    dim3 pgrid(NTOK / 128, BATCH);
    proj_mma<<<pgrid, 512, PRJ_SMEM>>>(x);

    dim3 agrid(NTOK / 64, BATCH);
    attn_mma<<<agrid, 256, ATT_SMEM>>>(x, alpha, out);
}

// round 15
// speedup vs baseline: 1.1388x; 1.1388x over previous
#include <cuda_runtime.h>
#include <cuda_bf16.h>
#include <cstdint>

// ---------------------------------------------------------------------------
// ChannelWise position-attention via generic mma.sync (compute_103-safe).
//   Q = feat_b^T [N,32] bf16 (pre-scaled by log2e), K = feat_c^T [N,32] bf16,
//   V = feat_d channel-major [256,N] bf16,  N = 4096, B = 4.
//   out = alpha * (softmax(QK^T) V)^T + (1-alpha) * x
// Pool FUSED into projection GEMM (bf16 mma); attention all-bf16 mma
// (S m16n8k16, PV m16n8k16) saturating the legacy-HMMA pipe (R13 config,
// measured best: both smaller and larger CTA shapes regress).
// ---------------------------------------------------------------------------

#define NTOK 4096
#define BATCH 4
#define NEG_BIG (-3.402823466e38f)
#define LOG2E 1.4426950408889634f

__device__ __nv_bfloat16 g_wb16[320 * 512];            // [o][k] bf16
__device__ float g_bias[320];
__device__ __nv_bfloat16 g_qb[BATCH * NTOK * 32];      // [b][n][32] (x log2e)
__device__ __nv_bfloat16 g_kb[BATCH * NTOK * 32];      // [b][n][32]
__device__ __nv_bfloat16 g_vb[BATCH * 256 * NTOK];     // [b][c][n]

extern __shared__ char smem_dyn[];

// ======================= PTX helpers ======================================
__device__ __forceinline__ uint32_t smem_u32(const void* p) {
    uint32_t a;
    asm("{ .reg .u64 t; cvta.to.shared.u64 t, %1; cvt.u32.u64 %0, t; }"
        : "=r"(a) : "l"(p));
    return a;
}
__device__ __forceinline__ uint32_t pack_bf16x2(float lo, float hi) {
    uint32_t r;
    asm("cvt.rn.bf16x2.f32 %0, %1, %2;" : "=r"(r) : "f"(hi), "f"(lo));
    return r;
}
__device__ __forceinline__ float ex2(float x) {
    float y;
    asm("ex2.approx.f32 %0, %1;" : "=f"(y) : "f"(x));
    return y;
}
__device__ __forceinline__ void ldsm4(uint32_t r[4], uint32_t addr) {
    asm volatile("ldmatrix.sync.aligned.m8n8.x4.shared.b16 {%0,%1,%2,%3}, [%4];"
                 : "=r"(r[0]), "=r"(r[1]), "=r"(r[2]), "=r"(r[3]) : "r"(addr));
}
__device__ __forceinline__ void ldsm4t(uint32_t r[4], uint32_t addr) {
    asm volatile(
        "ldmatrix.sync.aligned.m8n8.x4.trans.shared.b16 {%0,%1,%2,%3}, [%4];"
        : "=r"(r[0]), "=r"(r[1]), "=r"(r[2]), "=r"(r[3]) : "r"(addr));
}
__device__ __forceinline__ void mma_bf16(float d[4], const uint32_t a[4],
                                         uint32_t b0, uint32_t b1) {
    asm volatile(
        "mma.sync.aligned.m16n8k16.row.col.f32.bf16.bf16.f32 "
        "{%0,%1,%2,%3},{%4,%5,%6,%7},{%8,%9},{%0,%1,%2,%3};"
        : "+f"(d[0]), "+f"(d[1]), "+f"(d[2]), "+f"(d[3])
        : "r"(a[0]), "r"(a[1]), "r"(a[2]), "r"(a[3]), "r"(b0), "r"(b1));
}
__device__ __forceinline__ void cp16(uint32_t dst, const void* src) {
    asm volatile("cp.async.cg.shared.global [%0], [%1], 16;"
                 :: "r"(dst), "l"(src));
}
#define CP_COMMIT() asm volatile("cp.async.commit_group;" ::: "memory")
#define CP_WAIT0()  asm volatile("cp.async.wait_group 0;" ::: "memory")

// ---------------------------------------------------------------------------
// Kernel 1: W -> bf16 [o][k] + bias. 80 blocks x 512 thr, float4 per thread.
// ---------------------------------------------------------------------------
__global__ void prep_w(const float* __restrict__ wb, const float* __restrict__ bb,
                       const float* __restrict__ wc, const float* __restrict__ bc,
                       const float* __restrict__ wd, const float* __restrict__ bd) {
    int g = blockIdx.x * 512 + threadIdx.x;    // 320*128 = 40960 threads
    int o = g >> 7, k4 = (g & 127) << 2;
    const float* src;
    if (o < 32)       src = wb + o * 512;
    else if (o < 64)  src = wc + (o - 32) * 512;
    else              src = wd + (o - 64) * 512;
    float4 v = *(const float4*)(src + k4);
    *(uint2*)(g_wb16 + o * 512 + k4) =
        make_uint2(pack_bf16x2(v.x, v.y), pack_bf16x2(v.z, v.w));
    if ((g & 127) == 0)
        g_bias[o] = (o < 32) ? bb[o] : (o < 64 ? bc[o - 32] : bd[o - 64]);
}

// ---------------------------------------------------------------------------
// Kernel 2: FUSED pool + projection GEMM. CTA = 128 tokens x 320 outs, 512 thr.
// K processed as 8 channel-pairs: per pair, a 32-channel x slab (4 rows halo)
// is pooled in-smem into avg chunk and max chunk, then two bf16 mma passes.
// ---------------------------------------------------------------------------
#define XT(i)    ((i) * 34816)
#define CATA     69632
#define CATB     78336
#define PWA(i)   (87040 + (i) * 25600)
#define PWB(i)   (138240 + (i) * 25600)
#define PRJ_SMEM 189440

__global__ __launch_bounds__(512) void proj_mma(const float* __restrict__ xin) {
    const uint32_t sb = smem_u32(smem_dyn);
    const int tid = threadIdx.x, w = tid >> 5, l = tid & 31;
    const int mw = w >> 2, nw = w & 3;
    const int mt_base = mw * 32, o0w = nw * 80;
    const int ntile = blockIdx.x, b = blockIdx.y;
    const int n0 = ntile * 128;
    const int H0 = ntile * 2;
    const bool row0v = (ntile > 0);
    const bool row3v = (ntile < 31);
    const float* xg = xin + ((size_t)b << 20);

    float acc[2][10][4];
#pragma unroll
    for (int i = 0; i < 2; i++)
#pragma unroll
        for (int j = 0; j < 10; j++)
#pragma unroll
            for (int k = 0; k < 4; k++) acc[i][j][k] = 0.f;

#define PRJ_LOADX(buf, p_)                                                     \
    do {                                                                       \
        int pch_ = (p_) * 32;                                                  \
        _Pragma("unroll")                                                      \
        for (int i_ = 0; i_ < 4; ++i_) {                                       \
            int c_ = tid + i_ * 512;                                           \
            int ch_ = c_ >> 6, row_ = (c_ >> 4) & 3, pp_ = c_ & 15;            \
            uint32_t off_ =                                                    \
                (uint32_t)(XT(buf) + ch_ * 1088 + row_ * 272 + pp_ * 16);      \
            int hh_ = H0 - 1 + row_;                                           \
            if ((unsigned)hh_ < 64u)                                           \
                cp16(sb + off_,                                                \
                     xg + ((size_t)(pch_ + ch_) << 12) + (hh_ << 6) + pp_ * 4);\
            else                                                               \
                *(float4*)(smem_dyn + off_) = make_float4(0.f, 0.f, 0.f, 0.f); \
        }                                                                      \
        for (int e_ = tid; e_ < 1280; e_ += 512) {                             \
            int ro_ = e_ >> 2, pq_ = e_ & 3;                                   \
            cp16(sb + PWA(buf) + ro_ * 80 + pq_ * 16,                          \
                 g_wb16 + ro_ * 512 + pch_ + pq_ * 8);                         \
            cp16(sb + PWB(buf) + ro_ * 80 + pq_ * 16,                          \
                 g_wb16 + ro_ * 512 + 256 + pch_ + pq_ * 8);                   \
        }                                                                      \
    } while (0)

#define PRJ_MMA_CHUNK(cbase, wbase)                                            \
    do {                                                                       \
        _Pragma("unroll")                                                      \
        for (int ks = 0; ks < 2; ++ks) {                                       \
            uint32_t a_[2][4];                                                 \
            _Pragma("unroll")                                                  \
            for (int mt = 0; mt < 2; ++mt) {                                   \
                uint32_t addr_ = (cbase) +                                     \
                    (uint32_t)((ks * 16 + (l & 7) + ((l >> 4) << 3)) * 272 +   \
                               (mt_base + mt * 16 + (((l >> 3) & 1) << 3)) * 2);\
                ldsm4t(a_[mt], addr_);                                         \
            }                                                                  \
            _Pragma("unroll")                                                  \
            for (int bt = 0; bt < 5; ++bt) {                                   \
                uint32_t b4_[4];                                               \
                uint32_t addr_ = (wbase) +                                     \
                    (uint32_t)((o0w + bt * 16 + (l & 15)) * 80 + ks * 32 +     \
                               ((l >> 4) << 4));                               \
                ldsm4(b4_, addr_);                                             \
                mma_bf16(acc[0][bt * 2],     a_[0], b4_[0], b4_[2]);           \
                mma_bf16(acc[0][bt * 2 + 1], a_[0], b4_[1], b4_[3]);           \
                mma_bf16(acc[1][bt * 2],     a_[1], b4_[0], b4_[2]);           \
                mma_bf16(acc[1][bt * 2 + 1], a_[1], b4_[1], b4_[3]);           \
            }                                                                  \
        }                                                                      \
    } while (0)

    PRJ_LOADX(0, 0);
    CP_COMMIT();

    const int lane16 = l & 15;
    const int tr = (l >> 4) & 1;

#pragma unroll 1
    for (int p = 0; p < 8; ++p) {
        const int pb = p & 1;
        CP_WAIT0();
        __syncthreads();
        if (p + 1 < 8) {
            PRJ_LOADX((p + 1) & 1, p + 1);
            CP_COMMIT();
        }

        // ---- pool compute: XT(pb) -> CATA (avg), CATB (max) ----
        {
            const bool fA = (tr == 1) || row0v;
            const bool fC = (tr == 0) || row3v;
            const float inv9 = 1.f / 9.f;
#pragma unroll
            for (int i = 0; i < 2; ++i) {
                int ch = (tid + i * 512) >> 5;
                uint32_t xb =
                    (uint32_t)(XT(pb) + ch * 1088 + tr * 272 + lane16 * 16);
                float4 vA = *(const float4*)(smem_dyn + xb);
                float4 vB = *(const float4*)(smem_dyn + xb + 272);
                float4 vC = *(const float4*)(smem_dyn + xb + 544);
                float4 cs;
                cs.x = vA.x + vB.x + vC.x;
                cs.y = vA.y + vB.y + vC.y;
                cs.z = vA.z + vB.z + vC.z;
                cs.w = vA.w + vB.w + vC.w;
                float4 m4 = vB;
                if (fA) {
                    m4.x = fmaxf(m4.x, vA.x); m4.y = fmaxf(m4.y, vA.y);
                    m4.z = fmaxf(m4.z, vA.z); m4.w = fmaxf(m4.w, vA.w);
                }
                if (fC) {
                    m4.x = fmaxf(m4.x, vC.x); m4.y = fmaxf(m4.y, vC.y);
                    m4.z = fmaxf(m4.z, vC.z); m4.w = fmaxf(m4.w, vC.w);
                }
                float csL = __shfl_up_sync(0xffffffffu, cs.w, 1, 16);
                float mL  = __shfl_up_sync(0xffffffffu, m4.w, 1, 16);
                float csR = __shfl_down_sync(0xffffffffu, cs.x, 1, 16);
                float mR  = __shfl_down_sync(0xffffffffu, m4.x, 1, 16);
                if (lane16 == 0)  { csL = 0.f; mL = NEG_BIG; }
                if (lane16 == 15) { csR = 0.f; mR = NEG_BIG; }
                float a0 = (csL + cs.x + cs.y) * inv9;
                float a1 = (cs.x + cs.y + cs.z) * inv9;
                float a2 = (cs.y + cs.z + cs.w) * inv9;
                float a3 = (cs.z + cs.w + csR) * inv9;
                float M0 = fmaxf(fmaxf(mL, m4.x), m4.y);
                float M1 = fmaxf(fmaxf(m4.x, m4.y), m4.z);
                float M2 = fmaxf(fmaxf(m4.y, m4.z), m4.w);
                float M3 = fmaxf(fmaxf(m4.z, m4.w), mR);
                uint32_t co = (uint32_t)(ch * 272 + (tr * 64 + lane16 * 4) * 2);
                *(uint2*)(smem_dyn + CATA + co) =
                    make_uint2(pack_bf16x2(a0, a1), pack_bf16x2(a2, a3));
                *(uint2*)(smem_dyn + CATB + co) =
                    make_uint2(pack_bf16x2(M0, M1), pack_bf16x2(M2, M3));
            }
        }
        __syncthreads();

        PRJ_MMA_CHUNK(sb + CATA, sb + PWA(pb));
        PRJ_MMA_CHUNK(sb + CATB, sb + PWB(pb));
    }
    __syncthreads();

    // ---- epilogue: bias + fp32 stage [320][133], then routed stores ----
    float* stg = (float*)smem_dyn;
#pragma unroll
    for (int mt = 0; mt < 2; ++mt) {
        int m = mt_base + mt * 16 + (l >> 2);
#pragma unroll
        for (int t = 0; t < 10; ++t) {
            int o = o0w + t * 8 + (l & 3) * 2;
            float b0v = g_bias[o], b1v = g_bias[o + 1];
            stg[o * 133 + m]           = acc[mt][t][0] + b0v;
            stg[(o + 1) * 133 + m]     = acc[mt][t][1] + b1v;
            stg[o * 133 + m + 8]       = acc[mt][t][2] + b0v;
            stg[(o + 1) * 133 + m + 8] = acc[mt][t][3] + b1v;
        }
    }
    __syncthreads();
    // Q bf16 [n][32], pre-scaled by log2e
    for (int e = tid; e < 128 * 16; e += 512) {
        int o2 = e & 15, nl = e >> 4;
        *(uint32_t*)(g_qb + ((size_t)b * NTOK + n0 + nl) * 32 + 2 * o2) =
            pack_bf16x2(LOG2E * stg[(2 * o2) * 133 + nl],
                        LOG2E * stg[(2 * o2 + 1) * 133 + nl]);
    }
    // K bf16 [n][32]
    for (int e = tid; e < 128 * 16; e += 512) {
        int o2 = e & 15, nl = e >> 4;
        *(uint32_t*)(g_kb + ((size_t)b * NTOK + n0 + nl) * 32 + 2 * o2) =
            pack_bf16x2(stg[(32 + 2 * o2) * 133 + nl],
                        stg[(33 + 2 * o2) * 133 + nl]);
    }
    for (int e = tid; e < 256 * 64; e += 512) {
        int ch = e >> 6, tp = e & 63;
        float f0 = stg[(64 + ch) * 133 + 2 * tp];
        float f1 = stg[(64 + ch) * 133 + 2 * tp + 1];
        *(uint32_t*)(g_vb + ((size_t)(b * 256 + ch)) * NTOK + n0 + 2 * tp) =
            pack_bf16x2(f0, f1);
    }
}

// ---------------------------------------------------------------------------
// Kernel 3: mma.sync attention, all-bf16 (S m16n8k16 + PV m16n8k16).
// CTA = 128 query rows, 512 thr (16 warps), 64-token KV tiles, 1 wave.
// smem: K[2][64 tok][80B bf16] | V[2][256][144B] | P[128][144B] | L[128]f32
// ---------------------------------------------------------------------------
#define KOFF(i) ((i) * 5120)
#define VOFF(i) (10240 + (i) * 36864)
#define POFF 83968
#define LOFF 102400
#define ATT_SMEM 102912

__device__ __forceinline__ void load_tiles(uint32_t sb, int buf,
                                           const __nv_bfloat16* Kg,
                                           const __nv_bfloat16* Vg, int jt,
                                           int tid) {
    if (tid < 256) {                           // K: 64 tok x 64B, pitch 80
        const __nv_bfloat16* ks = Kg + (size_t)jt * 64 * 32;
        int tok = tid >> 2, p = tid & 3;
        cp16(sb + KOFF(buf) + tok * 80 + p * 16, ks + tok * 32 + p * 8);
    }
    const __nv_bfloat16* vs = Vg + jt * 64;
    uint32_t vd = sb + VOFF(buf);
#pragma unroll
    for (int i = 0; i < 4; ++i) {
        int c = tid + i * 512;
        int ch = c >> 3, p = c & 7;
        cp16(vd + ch * 144 + p * 16, vs + (size_t)ch * NTOK + p * 8);
    }
}

__global__ __launch_bounds__(512, 1) void attn_mma(
    const float* __restrict__ Xg, const float* __restrict__ alpha_p,
    float* __restrict__ Og) {
    const uint32_t sb = smem_u32(smem_dyn);
    float* Lsm = (float*)(smem_dyn + LOFF);
    const int tid = threadIdx.x, w = tid >> 5, l = tid & 31;
    const int rg = w & 7, th = w >> 3;         // S mapping
    const int wpv = w & 7, rh = w >> 3;        // PV mapping
    const int mt = blockIdx.x, b = blockIdx.y;
    const int m0 = mt * 128;
    const int r0 = l >> 2, kb = l & 3;

    if (tid < 128) Lsm[tid] = 0.f;

    // ---- Q bf16 A-fragments (2 k-steps), rows rg*16 + r0 (+8) ----
    uint32_t qa[2][4];
    {
        const uint32_t* Qg =
            (const uint32_t*)(g_qb + ((size_t)b * NTOK + m0 + rg * 16) * 32);
#pragma unroll
        for (int s_ = 0; s_ < 2; ++s_) {
            qa[s_][0] = Qg[r0 * 16 + s_ * 8 + kb];
            qa[s_][1] = Qg[(r0 + 8) * 16 + s_ * 8 + kb];
            qa[s_][2] = Qg[r0 * 16 + s_ * 8 + kb + 4];
            qa[s_][3] = Qg[(r0 + 8) * 16 + s_ * 8 + kb + 4];
        }
    }

    float o[2][8][4];
#pragma unroll
    for (int i = 0; i < 2; i++)
#pragma unroll
        for (int j = 0; j < 8; j++)
#pragma unroll
            for (int k = 0; k < 4; k++) o[i][j][k] = 0.f;

    const __nv_bfloat16* Kg = g_kb + (size_t)b * NTOK * 32;
    const __nv_bfloat16* Vg = g_vb + (size_t)b * 256 * NTOK;

    load_tiles(sb, 0, Kg, Vg, 0, tid);
    CP_COMMIT();

#pragma unroll 1
    for (int jt = 0; jt < 64; ++jt) {
        const int cur = jt & 1;
        CP_WAIT0();
        __syncthreads();
        if (jt + 1 < 64) {
            load_tiles(sb, 1 - cur, Kg, Vg, jt + 1, tid);
            CP_COMMIT();
        }
        const uint32_t* K32 = (const uint32_t*)(smem_dyn + KOFF(cur));
        const uint32_t* V32 = (const uint32_t*)(smem_dyn + VOFF(cur));
        uint32_t* P32 = (uint32_t*)(smem_dyn + POFF);

        // ---- S = Q K^T (bf16 m16n8k16, 8 mma; log2 domain) ----
        float s[4][4];
#pragma unroll
        for (int i = 0; i < 4; i++)
#pragma unroll
            for (int j = 0; j < 4; j++) s[i][j] = 0.f;
#pragma unroll
        for (int nt = 0; nt < 4; ++nt) {
            int trow = (th * 32 + nt * 8 + r0) * 20;   // 80B pitch = 20 u32
#pragma unroll
            for (int s_ = 0; s_ < 2; ++s_) {
                uint32_t b0 = K32[trow + s_ * 8 + kb];
                uint32_t b1 = K32[trow + s_ * 8 + kb + 4];
                mma_bf16(s[nt], qa[s_], b0, b1);
            }
        }

        // ---- exp2 (no shift; logits bounded), pack bf16 P, row-sum ----
        float t0 = 0.f, t1 = 0.f;
#pragma unroll
        for (int nt = 0; nt < 4; ++nt) {
            float p0 = ex2(s[nt][0]);
            float p1 = ex2(s[nt][1]);
            float p2 = ex2(s[nt][2]);
            float p3 = ex2(s[nt][3]);
            t0 += p0 + p1;
            t1 += p2 + p3;
            int tp = th * 16 + nt * 4 + kb;
            P32[(rg * 16 + r0) * 36 + tp] = pack_bf16x2(p0, p1);
            P32[(rg * 16 + r0 + 8) * 36 + tp] = pack_bf16x2(p2, p3);
        }
        t0 += __shfl_xor_sync(0xffffffffu, t0, 1);
        t0 += __shfl_xor_sync(0xffffffffu, t0, 2);
        t1 += __shfl_xor_sync(0xffffffffu, t1, 1);
        t1 += __shfl_xor_sync(0xffffffffu, t1, 2);
        if (kb == 0) {
            atomicAdd(&Lsm[rg * 16 + r0], t0);
            atomicAdd(&Lsm[rg * 16 + r0 + 8], t1);
        }
        __syncthreads();

        // ---- O^T += V' P^T (bf16 mma) ----
        uint32_t va[2][4][4];
#pragma unroll
        for (int m = 0; m < 2; ++m) {
            int cb = wpv * 32 + m * 16;
#pragma unroll
            for (int ks = 0; ks < 4; ++ks) {
                va[m][ks][0] = V32[(cb + r0) * 36 + ks * 8 + kb];
                va[m][ks][1] = V32[(cb + 8 + r0) * 36 + ks * 8 + kb];
                va[m][ks][2] = V32[(cb + r0) * 36 + ks * 8 + 4 + kb];
                va[m][ks][3] = V32[(cb + 8 + r0) * 36 + ks * 8 + 4 + kb];
            }
        }
#pragma unroll
        for (int nt = 0; nt < 8; ++nt) {
            int prow = rh * 64 + nt * 8 + r0;
#pragma unroll
            for (int ks = 0; ks < 4; ++ks) {
                uint32_t b0 = P32[prow * 36 + ks * 8 + kb];
                uint32_t b1 = P32[prow * 36 + ks * 8 + 4 + kb];
                mma_bf16(o[0][nt], va[0][ks], b0, b1);
                mma_bf16(o[1][nt], va[1][ks], b0, b1);
            }
        }
    }
    __syncthreads();

    // ---- epilogue ----
    float alpha = *alpha_p;
    if (tid < 128) Lsm[tid] = alpha / Lsm[tid];
    __syncthreads();
    float beta = 1.0f - alpha;
#pragma unroll
    for (int m = 0; m < 2; ++m) {
        int ch = wpv * 32 + m * 16 + r0;
#pragma unroll
        for (int nt = 0; nt < 8; ++nt) {
            int r = rh * 64 + nt * 8 + 2 * kb;
            float i0 = Lsm[r], i1 = Lsm[r + 1];
            size_t g0 = ((size_t)(b * 256 + ch)) * NTOK + m0 + r;
            float2 xv = *(const float2*)(Xg + g0);
            float2 ov = make_float2(o[m][nt][0] * i0 + beta * xv.x,
                                    o[m][nt][1] * i1 + beta * xv.y);
            *(float2*)(Og + g0) = ov;
            size_t g1 = g0 + (size_t)8 * NTOK;
            float2 xv2 = *(const float2*)(Xg + g1);
            float2 ov2 = make_float2(o[m][nt][2] * i0 + beta * xv2.x,
                                     o[m][nt][3] * i1 + beta * xv2.y);
            *(float2*)(Og + g1) = ov2;
        }
    }
}

// ---------------------------------------------------------------------------
extern "C" void kernel_launch(void* const* d_in, const int* in_sizes, int n_in,
                              void* d_out, int out_size) {
    const float* x     = (const float*)d_in[0];
    const float* wb    = (const float*)d_in[1];
    const float* bb    = (const float*)d_in[2];
    const float* wc    = (const float*)d_in[3];
    const float* bc    = (const float*)d_in[4];
    const float* wd    = (const float*)d_in[5];
    const float* bd    = (const float*)d_in[6];
    const float* alpha = (const float*)d_in[7];
    float* out = (float*)d_out;

    cudaFuncSetAttribute(proj_mma, cudaFuncAttributeMaxDynamicSharedMemorySize,
                         PRJ_SMEM);
    cudaFuncSetAttribute(attn_mma, cudaFuncAttributeMaxDynamicSharedMemorySize,
                         ATT_SMEM);

    prep_w<<<80, 512>>>(wb, bb, wc, bc, wd, bd);

    dim3 pgrid(NTOK / 128, BATCH);
    proj_mma<<<pgrid, 512, PRJ_SMEM>>>(x);

    dim3 agrid(NTOK / 128, BATCH);
    attn_mma<<<agrid, 512, ATT_SMEM>>>(x, alpha, out);
}

// round 16
// speedup vs baseline: 1.1942x; 1.0487x over previous
#include <cuda_runtime.h>
#include <cuda_bf16.h>
#include <cstdint>

// ---------------------------------------------------------------------------
// ChannelWise position-attention via generic mma.sync (compute_103-safe).
//   Q = feat_b^T [N,32] bf16 (pre-scaled by log2e), K = feat_c^T [N,32] bf16,
//   V = feat_d channel-major [256,N] bf16,  N = 4096, B = 4.
//   out = alpha * (softmax(QK^T) V)^T + (1-alpha) * x
// Pool FUSED into projection GEMM (bf16 mma); attention all-bf16 mma
// (S m16n8k16, PV m16n8k16) saturating the legacy-HMMA pipe. PV loop is
// ks-outer to maximize accumulator reuse distance (bit-identical math).
// ---------------------------------------------------------------------------

#define NTOK 4096
#define BATCH 4
#define NEG_BIG (-3.402823466e38f)
#define LOG2E 1.4426950408889634f

__device__ __nv_bfloat16 g_wb16[320 * 512];            // [o][k] bf16
__device__ float g_bias[320];
__device__ __nv_bfloat16 g_qb[BATCH * NTOK * 32];      // [b][n][32] (x log2e)
__device__ __nv_bfloat16 g_kb[BATCH * NTOK * 32];      // [b][n][32]
__device__ __nv_bfloat16 g_vb[BATCH * 256 * NTOK];     // [b][c][n]

extern __shared__ char smem_dyn[];

// ======================= PTX helpers ======================================
__device__ __forceinline__ uint32_t smem_u32(const void* p) {
    uint32_t a;
    asm("{ .reg .u64 t; cvta.to.shared.u64 t, %1; cvt.u32.u64 %0, t; }"
        : "=r"(a) : "l"(p));
    return a;
}
__device__ __forceinline__ uint32_t pack_bf16x2(float lo, float hi) {
    uint32_t r;
    asm("cvt.rn.bf16x2.f32 %0, %1, %2;" : "=r"(r) : "f"(hi), "f"(lo));
    return r;
}
__device__ __forceinline__ float ex2(float x) {
    float y;
    asm("ex2.approx.f32 %0, %1;" : "=f"(y) : "f"(x));
    return y;
}
__device__ __forceinline__ void ldsm4(uint32_t r[4], uint32_t addr) {
    asm volatile("ldmatrix.sync.aligned.m8n8.x4.shared.b16 {%0,%1,%2,%3}, [%4];"
                 : "=r"(r[0]), "=r"(r[1]), "=r"(r[2]), "=r"(r[3]) : "r"(addr));
}
__device__ __forceinline__ void ldsm4t(uint32_t r[4], uint32_t addr) {
    asm volatile(
        "ldmatrix.sync.aligned.m8n8.x4.trans.shared.b16 {%0,%1,%2,%3}, [%4];"
        : "=r"(r[0]), "=r"(r[1]), "=r"(r[2]), "=r"(r[3]) : "r"(addr));
}
__device__ __forceinline__ void mma_bf16(float d[4], const uint32_t a[4],
                                         uint32_t b0, uint32_t b1) {
    asm volatile(
        "mma.sync.aligned.m16n8k16.row.col.f32.bf16.bf16.f32 "
        "{%0,%1,%2,%3},{%4,%5,%6,%7},{%8,%9},{%0,%1,%2,%3};"
        : "+f"(d[0]), "+f"(d[1]), "+f"(d[2]), "+f"(d[3])
        : "r"(a[0]), "r"(a[1]), "r"(a[2]), "r"(a[3]), "r"(b0), "r"(b1));
}
__device__ __forceinline__ void cp16(uint32_t dst, const void* src) {
    asm volatile("cp.async.cg.shared.global [%0], [%1], 16;"
                 :: "r"(dst), "l"(src));
}
#define CP_COMMIT() asm volatile("cp.async.commit_group;" ::: "memory")
#define CP_WAIT0()  asm volatile("cp.async.wait_group 0;" ::: "memory")

// ---------------------------------------------------------------------------
// Kernel 1: W -> bf16 [o][k] + bias. 80 blocks x 512 thr, float4 per thread.
// ---------------------------------------------------------------------------
__global__ void prep_w(const float* __restrict__ wb, const float* __restrict__ bb,
                       const float* __restrict__ wc, const float* __restrict__ bc,
                       const float* __restrict__ wd, const float* __restrict__ bd) {
    int g = blockIdx.x * 512 + threadIdx.x;    // 320*128 = 40960 threads
    int o = g >> 7, k4 = (g & 127) << 2;
    const float* src;
    if (o < 32)       src = wb + o * 512;
    else if (o < 64)  src = wc + (o - 32) * 512;
    else              src = wd + (o - 64) * 512;
    float4 v = *(const float4*)(src + k4);
    *(uint2*)(g_wb16 + o * 512 + k4) =
        make_uint2(pack_bf16x2(v.x, v.y), pack_bf16x2(v.z, v.w));
    if ((g & 127) == 0)
        g_bias[o] = (o < 32) ? bb[o] : (o < 64 ? bc[o - 32] : bd[o - 64]);
}

// ---------------------------------------------------------------------------
// Kernel 2: FUSED pool + projection GEMM. CTA = 128 tokens x 320 outs, 512 thr.
// ---------------------------------------------------------------------------
#define XT(i)    ((i) * 34816)
#define CATA     69632
#define CATB     78336
#define PWA(i)   (87040 + (i) * 25600)
#define PWB(i)   (138240 + (i) * 25600)
#define PRJ_SMEM 189440

__global__ __launch_bounds__(512) void proj_mma(const float* __restrict__ xin) {
    const uint32_t sb = smem_u32(smem_dyn);
    const int tid = threadIdx.x, w = tid >> 5, l = tid & 31;
    const int mw = w >> 2, nw = w & 3;
    const int mt_base = mw * 32, o0w = nw * 80;
    const int ntile = blockIdx.x, b = blockIdx.y;
    const int n0 = ntile * 128;
    const int H0 = ntile * 2;
    const bool row0v = (ntile > 0);
    const bool row3v = (ntile < 31);
    const float* xg = xin + ((size_t)b << 20);

    float acc[2][10][4];
#pragma unroll
    for (int i = 0; i < 2; i++)
#pragma unroll
        for (int j = 0; j < 10; j++)
#pragma unroll
            for (int k = 0; k < 4; k++) acc[i][j][k] = 0.f;

#define PRJ_LOADX(buf, p_)                                                     \
    do {                                                                       \
        int pch_ = (p_) * 32;                                                  \
        _Pragma("unroll")                                                      \
        for (int i_ = 0; i_ < 4; ++i_) {                                       \
            int c_ = tid + i_ * 512;                                           \
            int ch_ = c_ >> 6, row_ = (c_ >> 4) & 3, pp_ = c_ & 15;            \
            uint32_t off_ =                                                    \
                (uint32_t)(XT(buf) + ch_ * 1088 + row_ * 272 + pp_ * 16);      \
            int hh_ = H0 - 1 + row_;                                           \
            if ((unsigned)hh_ < 64u)                                           \
                cp16(sb + off_,                                                \
                     xg + ((size_t)(pch_ + ch_) << 12) + (hh_ << 6) + pp_ * 4);\
            else                                                               \
                *(float4*)(smem_dyn + off_) = make_float4(0.f, 0.f, 0.f, 0.f); \
        }                                                                      \
        for (int e_ = tid; e_ < 1280; e_ += 512) {                             \
            int ro_ = e_ >> 2, pq_ = e_ & 3;                                   \
            cp16(sb + PWA(buf) + ro_ * 80 + pq_ * 16,                          \
                 g_wb16 + ro_ * 512 + pch_ + pq_ * 8);                         \
            cp16(sb + PWB(buf) + ro_ * 80 + pq_ * 16,                          \
                 g_wb16 + ro_ * 512 + 256 + pch_ + pq_ * 8);                   \
        }                                                                      \
    } while (0)

#define PRJ_MMA_CHUNK(cbase, wbase)                                            \
    do {                                                                       \
        _Pragma("unroll")                                                      \
        for (int ks = 0; ks < 2; ++ks) {                                       \
            uint32_t a_[2][4];                                                 \
            _Pragma("unroll")                                                  \
            for (int mt = 0; mt < 2; ++mt) {                                   \
                uint32_t addr_ = (cbase) +                                     \
                    (uint32_t)((ks * 16 + (l & 7) + ((l >> 4) << 3)) * 272 +   \
                               (mt_base + mt * 16 + (((l >> 3) & 1) << 3)) * 2);\
                ldsm4t(a_[mt], addr_);                                         \
            }                                                                  \
            _Pragma("unroll")                                                  \
            for (int bt = 0; bt < 5; ++bt) {                                   \
                uint32_t b4_[4];                                               \
                uint32_t addr_ = (wbase) +                                     \
                    (uint32_t)((o0w + bt * 16 + (l & 15)) * 80 + ks * 32 +     \
                               ((l >> 4) << 4));                               \
                ldsm4(b4_, addr_);                                             \
                mma_bf16(acc[0][bt * 2],     a_[0], b4_[0], b4_[2]);           \
                mma_bf16(acc[0][bt * 2 + 1], a_[0], b4_[1], b4_[3]);           \
                mma_bf16(acc[1][bt * 2],     a_[1], b4_[0], b4_[2]);           \
                mma_bf16(acc[1][bt * 2 + 1], a_[1], b4_[1], b4_[3]);           \
            }                                                                  \
        }                                                                      \
    } while (0)

    PRJ_LOADX(0, 0);
    CP_COMMIT();

    const int lane16 = l & 15;
    const int tr = (l >> 4) & 1;

#pragma unroll 1
    for (int p = 0; p < 8; ++p) {
        const int pb = p & 1;
        CP_WAIT0();
        __syncthreads();
        if (p + 1 < 8) {
            PRJ_LOADX((p + 1) & 1, p + 1);
            CP_COMMIT();
        }

        // ---- pool compute: XT(pb) -> CATA (avg), CATB (max) ----
        {
            const bool fA = (tr == 1) || row0v;
            const bool fC = (tr == 0) || row3v;
            const float inv9 = 1.f / 9.f;
#pragma unroll
            for (int i = 0; i < 2; ++i) {
                int ch = (tid + i * 512) >> 5;
                uint32_t xb =
                    (uint32_t)(XT(pb) + ch * 1088 + tr * 272 + lane16 * 16);
                float4 vA = *(const float4*)(smem_dyn + xb);
                float4 vB = *(const float4*)(smem_dyn + xb + 272);
                float4 vC = *(const float4*)(smem_dyn + xb + 544);
                float4 cs;
                cs.x = vA.x + vB.x + vC.x;
                cs.y = vA.y + vB.y + vC.y;
                cs.z = vA.z + vB.z + vC.z;
                cs.w = vA.w + vB.w + vC.w;
                float4 m4 = vB;
                if (fA) {
                    m4.x = fmaxf(m4.x, vA.x); m4.y = fmaxf(m4.y, vA.y);
                    m4.z = fmaxf(m4.z, vA.z); m4.w = fmaxf(m4.w, vA.w);
                }
                if (fC) {
                    m4.x = fmaxf(m4.x, vC.x); m4.y = fmaxf(m4.y, vC.y);
                    m4.z = fmaxf(m4.z, vC.z); m4.w = fmaxf(m4.w, vC.w);
                }
                float csL = __shfl_up_sync(0xffffffffu, cs.w, 1, 16);
                float mL  = __shfl_up_sync(0xffffffffu, m4.w, 1, 16);
                float csR = __shfl_down_sync(0xffffffffu, cs.x, 1, 16);
                float mR  = __shfl_down_sync(0xffffffffu, m4.x, 1, 16);
                if (lane16 == 0)  { csL = 0.f; mL = NEG_BIG; }
                if (lane16 == 15) { csR = 0.f; mR = NEG_BIG; }
                float a0 = (csL + cs.x + cs.y) * inv9;
                float a1 = (cs.x + cs.y + cs.z) * inv9;
                float a2 = (cs.y + cs.z + cs.w) * inv9;
                float a3 = (cs.z + cs.w + csR) * inv9;
                float M0 = fmaxf(fmaxf(mL, m4.x), m4.y);
                float M1 = fmaxf(fmaxf(m4.x, m4.y), m4.z);
                float M2 = fmaxf(fmaxf(m4.y, m4.z), m4.w);
                float M3 = fmaxf(fmaxf(m4.z, m4.w), mR);
                uint32_t co = (uint32_t)(ch * 272 + (tr * 64 + lane16 * 4) * 2);
                *(uint2*)(smem_dyn + CATA + co) =
                    make_uint2(pack_bf16x2(a0, a1), pack_bf16x2(a2, a3));
                *(uint2*)(smem_dyn + CATB + co) =
                    make_uint2(pack_bf16x2(M0, M1), pack_bf16x2(M2, M3));
            }
        }
        __syncthreads();

        PRJ_MMA_CHUNK(sb + CATA, sb + PWA(pb));
        PRJ_MMA_CHUNK(sb + CATB, sb + PWB(pb));
    }
    __syncthreads();

    // ---- epilogue: bias + fp32 stage [320][133], then routed stores ----
    float* stg = (float*)smem_dyn;
#pragma unroll
    for (int mt = 0; mt < 2; ++mt) {
        int m = mt_base + mt * 16 + (l >> 2);
#pragma unroll
        for (int t = 0; t < 10; ++t) {
            int o = o0w + t * 8 + (l & 3) * 2;
            float b0v = g_bias[o], b1v = g_bias[o + 1];
            stg[o * 133 + m]           = acc[mt][t][0] + b0v;
            stg[(o + 1) * 133 + m]     = acc[mt][t][1] + b1v;
            stg[o * 133 + m + 8]       = acc[mt][t][2] + b0v;
            stg[(o + 1) * 133 + m + 8] = acc[mt][t][3] + b1v;
        }
    }
    __syncthreads();
    // Q bf16 [n][32], pre-scaled by log2e
    for (int e = tid; e < 128 * 16; e += 512) {
        int o2 = e & 15, nl = e >> 4;
        *(uint32_t*)(g_qb + ((size_t)b * NTOK + n0 + nl) * 32 + 2 * o2) =
            pack_bf16x2(LOG2E * stg[(2 * o2) * 133 + nl],
                        LOG2E * stg[(2 * o2 + 1) * 133 + nl]);
    }
    // K bf16 [n][32]
    for (int e = tid; e < 128 * 16; e += 512) {
        int o2 = e & 15, nl = e >> 4;
        *(uint32_t*)(g_kb + ((size_t)b * NTOK + n0 + nl) * 32 + 2 * o2) =
            pack_bf16x2(stg[(32 + 2 * o2) * 133 + nl],
                        stg[(33 + 2 * o2) * 133 + nl]);
    }
    for (int e = tid; e < 256 * 64; e += 512) {
        int ch = e >> 6, tp = e & 63;
        float f0 = stg[(64 + ch) * 133 + 2 * tp];
        float f1 = stg[(64 + ch) * 133 + 2 * tp + 1];
        *(uint32_t*)(g_vb + ((size_t)(b * 256 + ch)) * NTOK + n0 + 2 * tp) =
            pack_bf16x2(f0, f1);
    }
}

// ---------------------------------------------------------------------------
// Kernel 3: mma.sync attention, all-bf16 (S m16n8k16 + PV m16n8k16).
// CTA = 128 query rows, 512 thr (16 warps), 64-token KV tiles, 1 wave.
// PV loop ks-outer: accumulator reuse distance 16 mma (bit-identical math).
// smem: K[2][64 tok][80B bf16] | V[2][256][144B] | P[128][144B] | L[128]f32
// ---------------------------------------------------------------------------
#define KOFF(i) ((i) * 5120)
#define VOFF(i) (10240 + (i) * 36864)
#define POFF 83968
#define LOFF 102400
#define ATT_SMEM 102912

__device__ __forceinline__ void load_tiles(uint32_t sb, int buf,
                                           const __nv_bfloat16* Kg,
                                           const __nv_bfloat16* Vg, int jt,
                                           int tid) {
    if (tid < 256) {                           // K: 64 tok x 64B, pitch 80
        const __nv_bfloat16* ks = Kg + (size_t)jt * 64 * 32;
        int tok = tid >> 2, p = tid & 3;
        cp16(sb + KOFF(buf) + tok * 80 + p * 16, ks + tok * 32 + p * 8);
    }
    const __nv_bfloat16* vs = Vg + jt * 64;
    uint32_t vd = sb + VOFF(buf);
#pragma unroll
    for (int i = 0; i < 4; ++i) {
        int c = tid + i * 512;
        int ch = c >> 3, p = c & 7;
        cp16(vd + ch * 144 + p * 16, vs + (size_t)ch * NTOK + p * 8);
    }
}

__global__ __launch_bounds__(512, 1) void attn_mma(
    const float* __restrict__ Xg, const float* __restrict__ alpha_p,
    float* __restrict__ Og) {
    const uint32_t sb = smem_u32(smem_dyn);
    float* Lsm = (float*)(smem_dyn + LOFF);
    const int tid = threadIdx.x, w = tid >> 5, l = tid & 31;
    const int rg = w & 7, th = w >> 3;         // S mapping
    const int wpv = w & 7, rh = w >> 3;        // PV mapping
    const int mt = blockIdx.x, b = blockIdx.y;
    const int m0 = mt * 128;
    const int r0 = l >> 2, kb = l & 3;

    if (tid < 128) Lsm[tid] = 0.f;

    // ---- Q bf16 A-fragments (2 k-steps), rows rg*16 + r0 (+8) ----
    uint32_t qa[2][4];
    {
        const uint32_t* Qg =
            (const uint32_t*)(g_qb + ((size_t)b * NTOK + m0 + rg * 16) * 32);
#pragma unroll
        for (int s_ = 0; s_ < 2; ++s_) {
            qa[s_][0] = Qg[r0 * 16 + s_ * 8 + kb];
            qa[s_][1] = Qg[(r0 + 8) * 16 + s_ * 8 + kb];
            qa[s_][2] = Qg[r0 * 16 + s_ * 8 + kb + 4];
            qa[s_][3] = Qg[(r0 + 8) * 16 + s_ * 8 + kb + 4];
        }
    }

    float o[2][8][4];
#pragma unroll
    for (int i = 0; i < 2; i++)
#pragma unroll
        for (int j = 0; j < 8; j++)
#pragma unroll
            for (int k = 0; k < 4; k++) o[i][j][k] = 0.f;

    const __nv_bfloat16* Kg = g_kb + (size_t)b * NTOK * 32;
    const __nv_bfloat16* Vg = g_vb + (size_t)b * 256 * NTOK;

    load_tiles(sb, 0, Kg, Vg, 0, tid);
    CP_COMMIT();

#pragma unroll 1
    for (int jt = 0; jt < 64; ++jt) {
        const int cur = jt & 1;
        CP_WAIT0();
        __syncthreads();
        if (jt + 1 < 64) {
            load_tiles(sb, 1 - cur, Kg, Vg, jt + 1, tid);
            CP_COMMIT();
        }
        const uint32_t* K32 = (const uint32_t*)(smem_dyn + KOFF(cur));
        const uint32_t* V32 = (const uint32_t*)(smem_dyn + VOFF(cur));
        uint32_t* P32 = (uint32_t*)(smem_dyn + POFF);

        // ---- S = Q K^T (bf16 m16n8k16, 8 mma; log2 domain) ----
        float s[4][4];
#pragma unroll
        for (int i = 0; i < 4; i++)
#pragma unroll
            for (int j = 0; j < 4; j++) s[i][j] = 0.f;
#pragma unroll
        for (int nt = 0; nt < 4; ++nt) {
            int trow = (th * 32 + nt * 8 + r0) * 20;   // 80B pitch = 20 u32
#pragma unroll
            for (int s_ = 0; s_ < 2; ++s_) {
                uint32_t b0 = K32[trow + s_ * 8 + kb];
                uint32_t b1 = K32[trow + s_ * 8 + kb + 4];
                mma_bf16(s[nt], qa[s_], b0, b1);
            }
        }

        // ---- exp2 (no shift; logits bounded), pack bf16 P, row-sum ----
        float t0 = 0.f, t1 = 0.f;
#pragma unroll
        for (int nt = 0; nt < 4; ++nt) {
            float p0 = ex2(s[nt][0]);
            float p1 = ex2(s[nt][1]);
            float p2 = ex2(s[nt][2]);
            float p3 = ex2(s[nt][3]);
            t0 += p0 + p1;
            t1 += p2 + p3;
            int tp = th * 16 + nt * 4 + kb;
            P32[(rg * 16 + r0) * 36 + tp] = pack_bf16x2(p0, p1);
            P32[(rg * 16 + r0 + 8) * 36 + tp] = pack_bf16x2(p2, p3);
        }
        t0 += __shfl_xor_sync(0xffffffffu, t0, 1);
        t0 += __shfl_xor_sync(0xffffffffu, t0, 2);
        t1 += __shfl_xor_sync(0xffffffffu, t1, 1);
        t1 += __shfl_xor_sync(0xffffffffu, t1, 2);
        if (kb == 0) {
            atomicAdd(&Lsm[rg * 16 + r0], t0);
            atomicAdd(&Lsm[rg * 16 + r0 + 8], t1);
        }
        __syncthreads();

        // ---- O^T += V' P^T (bf16 mma, ks-outer for long reuse distance) ----
        uint32_t va[2][4][4];
#pragma unroll
        for (int m = 0; m < 2; ++m) {
            int cb = wpv * 32 + m * 16;
#pragma unroll
            for (int ks = 0; ks < 4; ++ks) {
                va[m][ks][0] = V32[(cb + r0) * 36 + ks * 8 + kb];
                va[m][ks][1] = V32[(cb + 8 + r0) * 36 + ks * 8 + kb];
                va[m][ks][2] = V32[(cb + r0) * 36 + ks * 8 + 4 + kb];
                va[m][ks][3] = V32[(cb + 8 + r0) * 36 + ks * 8 + 4 + kb];
            }
        }
#pragma unroll
        for (int ks = 0; ks < 4; ++ks) {
#pragma unroll
            for (int nt = 0; nt < 8; ++nt) {
                int prow = rh * 64 + nt * 8 + r0;
                uint32_t b0 = P32[prow * 36 + ks * 8 + kb];
                uint32_t b1 = P32[prow * 36 + ks * 8 + 4 + kb];
                mma_bf16(o[0][nt], va[0][ks], b0, b1);
                mma_bf16(o[1][nt], va[1][ks], b0, b1);
            }
        }
    }
    __syncthreads();

    // ---- epilogue ----
    float alpha = *alpha_p;
    if (tid < 128) Lsm[tid] = alpha / Lsm[tid];
    __syncthreads();
    float beta = 1.0f - alpha;
#pragma unroll
    for (int m = 0; m < 2; ++m) {
        int ch = wpv * 32 + m * 16 + r0;
#pragma unroll
        for (int nt = 0; nt < 8; ++nt) {
            int r = rh * 64 + nt * 8 + 2 * kb;
            float i0 = Lsm[r], i1 = Lsm[r + 1];
            size_t g0 = ((size_t)(b * 256 + ch)) * NTOK + m0 + r;
            float2 xv = *(const float2*)(Xg + g0);
            float2 ov = make_float2(o[m][nt][0] * i0 + beta * xv.x,
                                    o[m][nt][1] * i1 + beta * xv.y);
            *(float2*)(Og + g0) = ov;
            size_t g1 = g0 + (size_t)8 * NTOK;
            float2 xv2 = *(const float2*)(Xg + g1);
            float2 ov2 = make_float2(o[m][nt][2] * i0 + beta * xv2.x,
                                     o[m][nt][3] * i1 + beta * xv2.y);
            *(float2*)(Og + g1) = ov2;
        }
    }
}

// ---------------------------------------------------------------------------
extern "C" void kernel_launch(void* const* d_in, const int* in_sizes, int n_in,
                              void* d_out, int out_size) {
    const float* x     = (const float*)d_in[0];
    const float* wb    = (const float*)d_in[1];
    const float* bb    = (const float*)d_in[2];
    const float* wc    = (const float*)d_in[3];
    const float* bc    = (const float*)d_in[4];
    const float* wd    = (const float*)d_in[5];
    const float* bd    = (const float*)d_in[6];
    const float* alpha = (const float*)d_in[7];
    float* out = (float*)d_out;

    cudaFuncSetAttribute(proj_mma, cudaFuncAttributeMaxDynamicSharedMemorySize,
                         PRJ_SMEM);
    cudaFuncSetAttribute(attn_mma, cudaFuncAttributeMaxDynamicSharedMemorySize,
                         ATT_SMEM);

    prep_w<<<80, 512>>>(wb, bb, wc, bc, wd, bd);

    dim3 pgrid(NTOK / 128, BATCH);
    proj_mma<<<pgrid, 512, PRJ_SMEM>>>(x);

    dim3 agrid(NTOK / 128, BATCH);
    attn_mma<<<agrid, 512, ATT_SMEM>>>(x, alpha, out);
}

// round 17
// speedup vs baseline: 1.1997x; 1.0046x over previous
#include <cuda_runtime.h>
#include <cuda_bf16.h>
#include <cstdint>

// ---------------------------------------------------------------------------
// ChannelWise position-attention via generic mma.sync (compute_103-safe).
//   Q = feat_b^T [N,32] bf16 (pre-scaled by log2e), K = feat_c^T [N,32] bf16,
//   V = feat_d channel-major [256,N] bf16,  N = 4096, B = 4.
//   out = alpha * (softmax(QK^T) V)^T + (1-alpha) * x
// Pool FUSED into projection GEMM (bf16 mma); attention all-bf16 mma
// (S m16n8k16, PV m16n8k16). Both mma loops use long-reuse-distance
// ordering (K-frags preloaded, s_-outer; PV ks-outer) — bit-identical math.
// ---------------------------------------------------------------------------

#define NTOK 4096
#define BATCH 4
#define NEG_BIG (-3.402823466e38f)
#define LOG2E 1.4426950408889634f

__device__ __nv_bfloat16 g_wb16[320 * 512];            // [o][k] bf16
__device__ float g_bias[320];
__device__ __nv_bfloat16 g_qb[BATCH * NTOK * 32];      // [b][n][32] (x log2e)
__device__ __nv_bfloat16 g_kb[BATCH * NTOK * 32];      // [b][n][32]
__device__ __nv_bfloat16 g_vb[BATCH * 256 * NTOK];     // [b][c][n]

extern __shared__ char smem_dyn[];

// ======================= PTX helpers ======================================
__device__ __forceinline__ uint32_t smem_u32(const void* p) {
    uint32_t a;
    asm("{ .reg .u64 t; cvta.to.shared.u64 t, %1; cvt.u32.u64 %0, t; }"
        : "=r"(a) : "l"(p));
    return a;
}
__device__ __forceinline__ uint32_t pack_bf16x2(float lo, float hi) {
    uint32_t r;
    asm("cvt.rn.bf16x2.f32 %0, %1, %2;" : "=r"(r) : "f"(hi), "f"(lo));
    return r;
}
__device__ __forceinline__ float ex2(float x) {
    float y;
    asm("ex2.approx.f32 %0, %1;" : "=f"(y) : "f"(x));
    return y;
}
__device__ __forceinline__ void ldsm4(uint32_t r[4], uint32_t addr) {
    asm volatile("ldmatrix.sync.aligned.m8n8.x4.shared.b16 {%0,%1,%2,%3}, [%4];"
                 : "=r"(r[0]), "=r"(r[1]), "=r"(r[2]), "=r"(r[3]) : "r"(addr));
}
__device__ __forceinline__ void ldsm4t(uint32_t r[4], uint32_t addr) {
    asm volatile(
        "ldmatrix.sync.aligned.m8n8.x4.trans.shared.b16 {%0,%1,%2,%3}, [%4];"
        : "=r"(r[0]), "=r"(r[1]), "=r"(r[2]), "=r"(r[3]) : "r"(addr));
}
__device__ __forceinline__ void mma_bf16(float d[4], const uint32_t a[4],
                                         uint32_t b0, uint32_t b1) {
    asm volatile(
        "mma.sync.aligned.m16n8k16.row.col.f32.bf16.bf16.f32 "
        "{%0,%1,%2,%3},{%4,%5,%6,%7},{%8,%9},{%0,%1,%2,%3};"
        : "+f"(d[0]), "+f"(d[1]), "+f"(d[2]), "+f"(d[3])
        : "r"(a[0]), "r"(a[1]), "r"(a[2]), "r"(a[3]), "r"(b0), "r"(b1));
}
__device__ __forceinline__ void cp16(uint32_t dst, const void* src) {
    asm volatile("cp.async.cg.shared.global [%0], [%1], 16;"
                 :: "r"(dst), "l"(src));
}
#define CP_COMMIT() asm volatile("cp.async.commit_group;" ::: "memory")
#define CP_WAIT0()  asm volatile("cp.async.wait_group 0;" ::: "memory")

// ---------------------------------------------------------------------------
// Kernel 1: W -> bf16 [o][k] + bias. 80 blocks x 512 thr, float4 per thread.
// ---------------------------------------------------------------------------
__global__ void prep_w(const float* __restrict__ wb, const float* __restrict__ bb,
                       const float* __restrict__ wc, const float* __restrict__ bc,
                       const float* __restrict__ wd, const float* __restrict__ bd) {
    int g = blockIdx.x * 512 + threadIdx.x;    // 320*128 = 40960 threads
    int o = g >> 7, k4 = (g & 127) << 2;
    const float* src;
    if (o < 32)       src = wb + o * 512;
    else if (o < 64)  src = wc + (o - 32) * 512;
    else              src = wd + (o - 64) * 512;
    float4 v = *(const float4*)(src + k4);
    *(uint2*)(g_wb16 + o * 512 + k4) =
        make_uint2(pack_bf16x2(v.x, v.y), pack_bf16x2(v.z, v.w));
    if ((g & 127) == 0)
        g_bias[o] = (o < 32) ? bb[o] : (o < 64 ? bc[o - 32] : bd[o - 64]);
}

// ---------------------------------------------------------------------------
// Kernel 2: FUSED pool + projection GEMM. CTA = 128 tokens x 320 outs, 512 thr.
// ---------------------------------------------------------------------------
#define XT(i)    ((i) * 34816)
#define CATA     69632
#define CATB     78336
#define PWA(i)   (87040 + (i) * 25600)
#define PWB(i)   (138240 + (i) * 25600)
#define PRJ_SMEM 189440

__global__ __launch_bounds__(512) void proj_mma(const float* __restrict__ xin) {
    const uint32_t sb = smem_u32(smem_dyn);
    const int tid = threadIdx.x, w = tid >> 5, l = tid & 31;
    const int mw = w >> 2, nw = w & 3;
    const int mt_base = mw * 32, o0w = nw * 80;
    const int ntile = blockIdx.x, b = blockIdx.y;
    const int n0 = ntile * 128;
    const int H0 = ntile * 2;
    const bool row0v = (ntile > 0);
    const bool row3v = (ntile < 31);
    const float* xg = xin + ((size_t)b << 20);

    float acc[2][10][4];
#pragma unroll
    for (int i = 0; i < 2; i++)
#pragma unroll
        for (int j = 0; j < 10; j++)
#pragma unroll
            for (int k = 0; k < 4; k++) acc[i][j][k] = 0.f;

#define PRJ_LOADX(buf, p_)                                                     \
    do {                                                                       \
        int pch_ = (p_) * 32;                                                  \
        _Pragma("unroll")                                                      \
        for (int i_ = 0; i_ < 4; ++i_) {                                       \
            int c_ = tid + i_ * 512;                                           \
            int ch_ = c_ >> 6, row_ = (c_ >> 4) & 3, pp_ = c_ & 15;            \
            uint32_t off_ =                                                    \
                (uint32_t)(XT(buf) + ch_ * 1088 + row_ * 272 + pp_ * 16);      \
            int hh_ = H0 - 1 + row_;                                           \
            if ((unsigned)hh_ < 64u)                                           \
                cp16(sb + off_,                                                \
                     xg + ((size_t)(pch_ + ch_) << 12) + (hh_ << 6) + pp_ * 4);\
            else                                                               \
                *(float4*)(smem_dyn + off_) = make_float4(0.f, 0.f, 0.f, 0.f); \
        }                                                                      \
        for (int e_ = tid; e_ < 1280; e_ += 512) {                             \
            int ro_ = e_ >> 2, pq_ = e_ & 3;                                   \
            cp16(sb + PWA(buf) + ro_ * 80 + pq_ * 16,                          \
                 g_wb16 + ro_ * 512 + pch_ + pq_ * 8);                         \
            cp16(sb + PWB(buf) + ro_ * 80 + pq_ * 16,                          \
                 g_wb16 + ro_ * 512 + 256 + pch_ + pq_ * 8);                   \
        }                                                                      \
    } while (0)

#define PRJ_MMA_CHUNK(cbase, wbase)                                            \
    do {                                                                       \
        _Pragma("unroll")                                                      \
        for (int ks = 0; ks < 2; ++ks) {                                       \
            uint32_t a_[2][4];                                                 \
            _Pragma("unroll")                                                  \
            for (int mt = 0; mt < 2; ++mt) {                                   \
                uint32_t addr_ = (cbase) +                                     \
                    (uint32_t)((ks * 16 + (l & 7) + ((l >> 4) << 3)) * 272 +   \
                               (mt_base + mt * 16 + (((l >> 3) & 1) << 3)) * 2);\
                ldsm4t(a_[mt], addr_);                                         \
            }                                                                  \
            _Pragma("unroll")                                                  \
            for (int bt = 0; bt < 5; ++bt) {                                   \
                uint32_t b4_[4];                                               \
                uint32_t addr_ = (wbase) +                                     \
                    (uint32_t)((o0w + bt * 16 + (l & 15)) * 80 + ks * 32 +     \
                               ((l >> 4) << 4));                               \
                ldsm4(b4_, addr_);                                             \
                mma_bf16(acc[0][bt * 2],     a_[0], b4_[0], b4_[2]);           \
                mma_bf16(acc[0][bt * 2 + 1], a_[0], b4_[1], b4_[3]);           \
                mma_bf16(acc[1][bt * 2],     a_[1], b4_[0], b4_[2]);           \
                mma_bf16(acc[1][bt * 2 + 1], a_[1], b4_[1], b4_[3]);           \
            }                                                                  \
        }                                                                      \
    } while (0)

    PRJ_LOADX(0, 0);
    CP_COMMIT();

    const int lane16 = l & 15;
    const int tr = (l >> 4) & 1;

#pragma unroll 1
    for (int p = 0; p < 8; ++p) {
        const int pb = p & 1;
        CP_WAIT0();
        __syncthreads();
        if (p + 1 < 8) {
            PRJ_LOADX((p + 1) & 1, p + 1);
            CP_COMMIT();
        }

        // ---- pool compute: XT(pb) -> CATA (avg), CATB (max) ----
        {
            const bool fA = (tr == 1) || row0v;
            const bool fC = (tr == 0) || row3v;
            const float inv9 = 1.f / 9.f;
#pragma unroll
            for (int i = 0; i < 2; ++i) {
                int ch = (tid + i * 512) >> 5;
                uint32_t xb =
                    (uint32_t)(XT(pb) + ch * 1088 + tr * 272 + lane16 * 16);
                float4 vA = *(const float4*)(smem_dyn + xb);
                float4 vB = *(const float4*)(smem_dyn + xb + 272);
                float4 vC = *(const float4*)(smem_dyn + xb + 544);
                float4 cs;
                cs.x = vA.x + vB.x + vC.x;
                cs.y = vA.y + vB.y + vC.y;
                cs.z = vA.z + vB.z + vC.z;
                cs.w = vA.w + vB.w + vC.w;
                float4 m4 = vB;
                if (fA) {
                    m4.x = fmaxf(m4.x, vA.x); m4.y = fmaxf(m4.y, vA.y);
                    m4.z = fmaxf(m4.z, vA.z); m4.w = fmaxf(m4.w, vA.w);
                }
                if (fC) {
                    m4.x = fmaxf(m4.x, vC.x); m4.y = fmaxf(m4.y, vC.y);
                    m4.z = fmaxf(m4.z, vC.z); m4.w = fmaxf(m4.w, vC.w);
                }
                float csL = __shfl_up_sync(0xffffffffu, cs.w, 1, 16);
                float mL  = __shfl_up_sync(0xffffffffu, m4.w, 1, 16);
                float csR = __shfl_down_sync(0xffffffffu, cs.x, 1, 16);
                float mR  = __shfl_down_sync(0xffffffffu, m4.x, 1, 16);
                if (lane16 == 0)  { csL = 0.f; mL = NEG_BIG; }
                if (lane16 == 15) { csR = 0.f; mR = NEG_BIG; }
                float a0 = (csL + cs.x + cs.y) * inv9;
                float a1 = (cs.x + cs.y + cs.z) * inv9;
                float a2 = (cs.y + cs.z + cs.w) * inv9;
                float a3 = (cs.z + cs.w + csR) * inv9;
                float M0 = fmaxf(fmaxf(mL, m4.x), m4.y);
                float M1 = fmaxf(fmaxf(m4.x, m4.y), m4.z);
                float M2 = fmaxf(fmaxf(m4.y, m4.z), m4.w);
                float M3 = fmaxf(fmaxf(m4.z, m4.w), mR);
                uint32_t co = (uint32_t)(ch * 272 + (tr * 64 + lane16 * 4) * 2);
                *(uint2*)(smem_dyn + CATA + co) =
                    make_uint2(pack_bf16x2(a0, a1), pack_bf16x2(a2, a3));
                *(uint2*)(smem_dyn + CATB + co) =
                    make_uint2(pack_bf16x2(M0, M1), pack_bf16x2(M2, M3));
            }
        }
        __syncthreads();

        PRJ_MMA_CHUNK(sb + CATA, sb + PWA(pb));
        PRJ_MMA_CHUNK(sb + CATB, sb + PWB(pb));
    }
    __syncthreads();

    // ---- epilogue: bias + fp32 stage [320][133], then routed stores ----
    float* stg = (float*)smem_dyn;
#pragma unroll
    for (int mt = 0; mt < 2; ++mt) {
        int m = mt_base + mt * 16 + (l >> 2);
#pragma unroll
        for (int t = 0; t < 10; ++t) {
            int o = o0w + t * 8 + (l & 3) * 2;
            float b0v = g_bias[o], b1v = g_bias[o + 1];
            stg[o * 133 + m]           = acc[mt][t][0] + b0v;
            stg[(o + 1) * 133 + m]     = acc[mt][t][1] + b1v;
            stg[o * 133 + m + 8]       = acc[mt][t][2] + b0v;
            stg[(o + 1) * 133 + m + 8] = acc[mt][t][3] + b1v;
        }
    }
    __syncthreads();
    // Q bf16 [n][32], pre-scaled by log2e
    for (int e = tid; e < 128 * 16; e += 512) {
        int o2 = e & 15, nl = e >> 4;
        *(uint32_t*)(g_qb + ((size_t)b * NTOK + n0 + nl) * 32 + 2 * o2) =
            pack_bf16x2(LOG2E * stg[(2 * o2) * 133 + nl],
                        LOG2E * stg[(2 * o2 + 1) * 133 + nl]);
    }
    // K bf16 [n][32]
    for (int e = tid; e < 128 * 16; e += 512) {
        int o2 = e & 15, nl = e >> 4;
        *(uint32_t*)(g_kb + ((size_t)b * NTOK + n0 + nl) * 32 + 2 * o2) =
            pack_bf16x2(stg[(32 + 2 * o2) * 133 + nl],
                        stg[(33 + 2 * o2) * 133 + nl]);
    }
    for (int e = tid; e < 256 * 64; e += 512) {
        int ch = e >> 6, tp = e & 63;
        float f0 = stg[(64 + ch) * 133 + 2 * tp];
        float f1 = stg[(64 + ch) * 133 + 2 * tp + 1];
        *(uint32_t*)(g_vb + ((size_t)(b * 256 + ch)) * NTOK + n0 + 2 * tp) =
            pack_bf16x2(f0, f1);
    }
}

// ---------------------------------------------------------------------------
// Kernel 3: mma.sync attention, all-bf16 (S m16n8k16 + PV m16n8k16).
// CTA = 128 query rows, 512 thr (16 warps), 64-token KV tiles, 1 wave.
// S loop: K-frags preloaded, s_-outer (reuse distance 4); PV loop ks-outer
// (reuse distance 16). Both bit-identical to the baseline math.
// smem: K[2][64 tok][80B bf16] | V[2][256][144B] | P[128][144B] | L[128]f32
// ---------------------------------------------------------------------------
#define KOFF(i) ((i) * 5120)
#define VOFF(i) (10240 + (i) * 36864)
#define POFF 83968
#define LOFF 102400
#define ATT_SMEM 102912

__device__ __forceinline__ void load_tiles(uint32_t sb, int buf,
                                           const __nv_bfloat16* Kg,
                                           const __nv_bfloat16* Vg, int jt,
                                           int tid) {
    if (tid < 256) {                           // K: 64 tok x 64B, pitch 80
        const __nv_bfloat16* ks = Kg + (size_t)jt * 64 * 32;
        int tok = tid >> 2, p = tid & 3;
        cp16(sb + KOFF(buf) + tok * 80 + p * 16, ks + tok * 32 + p * 8);
    }
    const __nv_bfloat16* vs = Vg + jt * 64;
    uint32_t vd = sb + VOFF(buf);
#pragma unroll
    for (int i = 0; i < 4; ++i) {
        int c = tid + i * 512;
        int ch = c >> 3, p = c & 7;
        cp16(vd + ch * 144 + p * 16, vs + (size_t)ch * NTOK + p * 8);
    }
}

__global__ __launch_bounds__(512, 1) void attn_mma(
    const float* __restrict__ Xg, const float* __restrict__ alpha_p,
    float* __restrict__ Og) {
    const uint32_t sb = smem_u32(smem_dyn);
    float* Lsm = (float*)(smem_dyn + LOFF);
    const int tid = threadIdx.x, w = tid >> 5, l = tid & 31;
    const int rg = w & 7, th = w >> 3;         // S mapping
    const int wpv = w & 7, rh = w >> 3;        // PV mapping
    const int mt = blockIdx.x, b = blockIdx.y;
    const int m0 = mt * 128;
    const int r0 = l >> 2, kb = l & 3;

    if (tid < 128) Lsm[tid] = 0.f;

    // ---- Q bf16 A-fragments (2 k-steps), rows rg*16 + r0 (+8) ----
    uint32_t qa[2][4];
    {
        const uint32_t* Qg =
            (const uint32_t*)(g_qb + ((size_t)b * NTOK + m0 + rg * 16) * 32);
#pragma unroll
        for (int s_ = 0; s_ < 2; ++s_) {
            qa[s_][0] = Qg[r0 * 16 + s_ * 8 + kb];
            qa[s_][1] = Qg[(r0 + 8) * 16 + s_ * 8 + kb];
            qa[s_][2] = Qg[r0 * 16 + s_ * 8 + kb + 4];
            qa[s_][3] = Qg[(r0 + 8) * 16 + s_ * 8 + kb + 4];
        }
    }

    float o[2][8][4];
#pragma unroll
    for (int i = 0; i < 2; i++)
#pragma unroll
        for (int j = 0; j < 8; j++)
#pragma unroll
            for (int k = 0; k < 4; k++) o[i][j][k] = 0.f;

    const __nv_bfloat16* Kg = g_kb + (size_t)b * NTOK * 32;
    const __nv_bfloat16* Vg = g_vb + (size_t)b * 256 * NTOK;

    load_tiles(sb, 0, Kg, Vg, 0, tid);
    CP_COMMIT();

#pragma unroll 1
    for (int jt = 0; jt < 64; ++jt) {
        const int cur = jt & 1;
        CP_WAIT0();
        __syncthreads();
        if (jt + 1 < 64) {
            load_tiles(sb, 1 - cur, Kg, Vg, jt + 1, tid);
            CP_COMMIT();
        }
        const uint32_t* K32 = (const uint32_t*)(smem_dyn + KOFF(cur));
        const uint32_t* V32 = (const uint32_t*)(smem_dyn + VOFF(cur));
        uint32_t* P32 = (uint32_t*)(smem_dyn + POFF);

        // ---- S = Q K^T (bf16 m16n8k16; K-frags preloaded, s_-outer) ----
        float s[4][4];
#pragma unroll
        for (int i = 0; i < 4; i++)
#pragma unroll
            for (int j = 0; j < 4; j++) s[i][j] = 0.f;
        uint32_t kf[4][2][2];                  // [nt][s_][b0/b1]
#pragma unroll
        for (int nt = 0; nt < 4; ++nt) {
            int trow = (th * 32 + nt * 8 + r0) * 20;   // 80B pitch = 20 u32
#pragma unroll
            for (int s_ = 0; s_ < 2; ++s_) {
                kf[nt][s_][0] = K32[trow + s_ * 8 + kb];
                kf[nt][s_][1] = K32[trow + s_ * 8 + kb + 4];
            }
        }
#pragma unroll
        for (int s_ = 0; s_ < 2; ++s_)
#pragma unroll
            for (int nt = 0; nt < 4; ++nt)
                mma_bf16(s[nt], qa[s_], kf[nt][s_][0], kf[nt][s_][1]);

        // ---- exp2 (no shift; logits bounded), pack bf16 P, row-sum ----
        float t0 = 0.f, t1 = 0.f;
#pragma unroll
        for (int nt = 0; nt < 4; ++nt) {
            float p0 = ex2(s[nt][0]);
            float p1 = ex2(s[nt][1]);
            float p2 = ex2(s[nt][2]);
            float p3 = ex2(s[nt][3]);
            t0 += p0 + p1;
            t1 += p2 + p3;
            int tp = th * 16 + nt * 4 + kb;
            P32[(rg * 16 + r0) * 36 + tp] = pack_bf16x2(p0, p1);
            P32[(rg * 16 + r0 + 8) * 36 + tp] = pack_bf16x2(p2, p3);
        }
        t0 += __shfl_xor_sync(0xffffffffu, t0, 1);
        t0 += __shfl_xor_sync(0xffffffffu, t0, 2);
        t1 += __shfl_xor_sync(0xffffffffu, t1, 1);
        t1 += __shfl_xor_sync(0xffffffffu, t1, 2);
        if (kb == 0) {
            atomicAdd(&Lsm[rg * 16 + r0], t0);
            atomicAdd(&Lsm[rg * 16 + r0 + 8], t1);
        }
        __syncthreads();

        // ---- O^T += V' P^T (bf16 mma, ks-outer for long reuse distance) ----
        uint32_t va[2][4][4];
#pragma unroll
        for (int m = 0; m < 2; ++m) {
            int cb = wpv * 32 + m * 16;
#pragma unroll
            for (int ks = 0; ks < 4; ++ks) {
                va[m][ks][0] = V32[(cb + r0) * 36 + ks * 8 + kb];
                va[m][ks][1] = V32[(cb + 8 + r0) * 36 + ks * 8 + kb];
                va[m][ks][2] = V32[(cb + r0) * 36 + ks * 8 + 4 + kb];
                va[m][ks][3] = V32[(cb + 8 + r0) * 36 + ks * 8 + 4 + kb];
            }
        }
#pragma unroll
        for (int ks = 0; ks < 4; ++ks) {
#pragma unroll
            for (int nt = 0; nt < 8; ++nt) {
                int prow = rh * 64 + nt * 8 + r0;
                uint32_t b0 = P32[prow * 36 + ks * 8 + kb];
                uint32_t b1 = P32[prow * 36 + ks * 8 + 4 + kb];
                mma_bf16(o[0][nt], va[0][ks], b0, b1);
                mma_bf16(o[1][nt], va[1][ks], b0, b1);
            }
        }
    }
    __syncthreads();

    // ---- epilogue ----
    float alpha = *alpha_p;
    if (tid < 128) Lsm[tid] = alpha / Lsm[tid];
    __syncthreads();
    float beta = 1.0f - alpha;
#pragma unroll
    for (int m = 0; m < 2; ++m) {
        int ch = wpv * 32 + m * 16 + r0;
#pragma unroll
        for (int nt = 0; nt < 8; ++nt) {
            int r = rh * 64 + nt * 8 + 2 * kb;
            float i0 = Lsm[r], i1 = Lsm[r + 1];
            size_t g0 = ((size_t)(b * 256 + ch)) * NTOK + m0 + r;
            float2 xv = *(const float2*)(Xg + g0);
            float2 ov = make_float2(o[m][nt][0] * i0 + beta * xv.x,
                                    o[m][nt][1] * i1 + beta * xv.y);
            *(float2*)(Og + g0) = ov;
            size_t g1 = g0 + (size_t)8 * NTOK;
            float2 xv2 = *(const float2*)(Xg + g1);
            float2 ov2 = make_float2(o[m][nt][2] * i0 + beta * xv2.x,
                                     o[m][nt][3] * i1 + beta * xv2.y);
            *(float2*)(Og + g1) = ov2;
        }
    }
}

// ---------------------------------------------------------------------------
extern "C" void kernel_launch(void* const* d_in, const int* in_sizes, int n_in,
                              void* d_out, int out_size) {
    const float* x     = (const float*)d_in[0];
    const float* wb    = (const float*)d_in[1];
    const float* bb    = (const float*)d_in[2];
    const float* wc    = (const float*)d_in[3];
    const float* bc    = (const float*)d_in[4];
    const float* wd    = (const float*)d_in[5];
    const float* bd    = (const float*)d_in[6];
    const float* alpha = (const float*)d_in[7];
    float* out = (float*)d_out;

    cudaFuncSetAttribute(proj_mma, cudaFuncAttributeMaxDynamicSharedMemorySize,
                         PRJ_SMEM);
    cudaFuncSetAttribute(attn_mma, cudaFuncAttributeMaxDynamicSharedMemorySize,
                         ATT_SMEM);

    prep_w<<<80, 512>>>(wb, bb, wc, bc, wd, bd);

    dim3 pgrid(NTOK / 128, BATCH);
    proj_mma<<<pgrid, 512, PRJ_SMEM>>>(x);

    dim3 agrid(NTOK / 128, BATCH);
    attn_mma<<<agrid, 512, ATT_SMEM>>>(x, alpha, out);
}